// round 13
// baseline (speedup 1.0000x reference)
#include <cuda_runtime.h>
#include <cstdint>

// Problem constants (from reference)
#define N_NODES 2000000
#define N_EDGES 32000000
#define N_OUT   400000   // N_NODES / 5
#define N_OUT4  100000   // N_OUT / 4

// Aggregation slots only for nodes with idx % 5 == 0 (1.6 MB, L2-resident).
// float4 for vector access in finalize; scatter uses a scalar float view.
// Zero-initialized at module load; finalize re-zeros it each replay.
__device__ float4 g_agg4[N_OUT4];

// --------------------------------------------------------------------------
// Scatter (frozen R8 structure + unsigned index math):
// 4 edges/thread, 8M threads, int4 loads for both streams,
// filter dst % 5, gather x[src], RED into agg[dst/5].
// --------------------------------------------------------------------------
__global__ void scatter_kernel(const float* __restrict__ x,
                               const int* __restrict__ src,
                               const int* __restrict__ dst) {
    float* agg = reinterpret_cast<float*>(g_agg4);
    long long base = (long long)(blockIdx.x * (long long)blockDim.x + threadIdx.x) * 4;
    if (base >= N_EDGES) return;

    int4 dv = *reinterpret_cast<const int4*>(dst + base);
    int4 sv = *reinterpret_cast<const int4*>(src + base);

    unsigned d[4] = { (unsigned)dv.x, (unsigned)dv.y, (unsigned)dv.z, (unsigned)dv.w };
    unsigned s[4] = { (unsigned)sv.x, (unsigned)sv.y, (unsigned)sv.z, (unsigned)sv.w };

#pragma unroll
    for (int k = 0; k < 4; k++) {
        if (d[k] % 5u == 0u) {
            float v = __ldg(x + s[k]);            // x[src] — L2 gather
            atomicAdd(&agg[d[k] / 5u], v);        // no return -> REDG to L2
        }
    }
}

// --------------------------------------------------------------------------
// Finalize (PDL): pre-dependency work = load the 17 scalar params and build
// collapsed-MLP coefficients (inputs, not produced by the scatter). Then
// grid-dependency sync, read g_agg, compute, reset, store float4.
// --------------------------------------------------------------------------
__global__ void finalize_kernel(const float* __restrict__ w_conv,
                                const float* __restrict__ b_conv,
                                const float* __restrict__ w1,
                                const float* __restrict__ b1,
                                const float* __restrict__ w2,
                                const float* __restrict__ b2,
                                float4* __restrict__ out) {
    int i = blockIdx.x * blockDim.x + threadIdx.x;

    // ---- pre-dependency work (overlaps the scatter's tail) ----
    float wc = __ldg(w_conv);
    float bc = __ldg(b_conv);
    float weff[4], bb1[4], ww2[4];
#pragma unroll
    for (int j = 0; j < 4; j++) {
        weff[j] = __ldg(w1 + j) + __ldg(w1 + 4 + j);   // w1 is [in=2, out=4]
        bb1[j]  = __ldg(b1 + j);
        ww2[j]  = __ldg(w2 + j);
    }
    float bb2 = __ldg(b2);

    // ---- wait for scatter's atomics to be visible ----
    cudaGridDependencySynchronize();

    if (i >= N_OUT4) return;
    float4 aggv = g_agg4[i];
    g_agg4[i] = make_float4(0.0f, 0.0f, 0.0f, 0.0f);   // reset for next replay

    float a[4] = { aggv.x, aggv.y, aggv.z, aggv.w };
    float r[4];
#pragma unroll
    for (int e = 0; e < 4; e++) {
        float av = fmaf(a[e], wc, bc);
        float acc = bb2;
#pragma unroll
        for (int j = 0; j < 4; j++) {
            float t = fmaxf(fmaf(av, weff[j], bb1[j]), 0.0f);
            acc = fmaf(t, ww2[j], acc);
        }
        r[e] = acc;
    }
    out[i] = make_float4(r[0], r[1], r[2], r[3]);
}

// --------------------------------------------------------------------------
// Launch
// inputs per metadata order:
//   d_in[0] x          (2,000,000 f32)
//   d_in[1] edge_index (2 x 32,000,000 int32, row-major: src row then dst row)
//   d_in[2] w_conv (1)  d_in[3] b_conv (1)
//   d_in[4] w1 (8)      d_in[5] b1 (4)
//   d_in[6] w2 (4)      d_in[7] b2 (1)
// output: 400,000 f32
// --------------------------------------------------------------------------
extern "C" void kernel_launch(void* const* d_in, const int* in_sizes, int n_in,
                              void* d_out, int out_size) {
    const float* x   = (const float*)d_in[0];
    const int*   ei  = (const int*)d_in[1];
    const int*   src = ei;
    const int*   dst = ei + N_EDGES;
    const float* w_conv = (const float*)d_in[2];
    const float* b_conv = (const float*)d_in[3];
    const float* w1     = (const float*)d_in[4];
    const float* b1     = (const float*)d_in[5];
    const float* w2     = (const float*)d_in[6];
    const float* b2     = (const float*)d_in[7];
    float4* out = (float4*)d_out;

    {
        int threads = 256;
        long long work = (long long)N_EDGES / 4;            // 8M threads, 4 edges each
        int blocks = (int)((work + threads - 1) / threads); // 31250
        scatter_kernel<<<blocks, threads>>>(x, src, dst);
    }
    {
        // Finalize with Programmatic Dependent Launch: overlap its launch/ramp
        // with the scatter's tail; correctness via cudaGridDependencySynchronize.
        cudaLaunchConfig_t cfg = {};
        cfg.gridDim  = dim3((N_OUT4 + 255) / 256);          // 391
        cfg.blockDim = dim3(256);
        cfg.dynamicSmemBytes = 0;
        cfg.stream = 0;
        cudaLaunchAttribute attrs[1];
        attrs[0].id = cudaLaunchAttributeProgrammaticStreamSerialization;
        attrs[0].val.programmaticStreamSerializationAllowed = 1;
        cfg.attrs = attrs;
        cfg.numAttrs = 1;
        cudaLaunchKernelEx(&cfg, finalize_kernel,
                           w_conv, b_conv, w1, b1, w2, b2, out);
    }
}